// round 11
// baseline (speedup 1.0000x reference)
#include <cuda_runtime.h>
#include <cuda_bf16.h>
#include <cstdint>

#define BATCH 64
#define TIN   128
#define FIN   64
#define HID   512
#define G4    2048
#define TOUTN 64
#define KLIN  32768
#define NLIN  4096
#define NBLK  128

#define KSPLIT 4
#define KPER   (KLIN / KSPLIT)
#define LCHUNK 64
#define LNCH   (KPER / LCHUNK)

// recurrence smem (u32 words): Wfrag 8192 | Ahi 64*260 | Alo 64*260 | Csm | red
#define WS_OFF  0
#define AHI_OFF 8192
#define ALO_OFF (AHI_OFF + 16640)
#define CSM_OFF (ALO_OFF + 16640)
#define RED_OFF (CSM_OFF + 1152)
#define DSMW    (RED_OFF + 1024)    // 42048 u32 = 168192 B

__device__ float g_xT[TIN * BATCH * FIN];
__device__ float g_pre1[TIN * BATCH * G4];
__device__ float g_pre2[BATCH * G4];
__device__ float g_hA[BATCH * HID];
__device__ float g_hB[BATCH * HID];
__device__ uint32_t g_hApk[BATCH * HID];
__device__ uint32_t g_hBpk[BATCH * HID];
__device__ float g_c[BATCH * HID];
__device__ float g_seq[BATCH * KLIN];
__device__ float g_part[KSPLIT * BATCH * NLIN];
__device__ __align__(32) unsigned g_ctr[8];

__device__ __forceinline__ uint32_t f2tf(float f) {
    uint32_t u;
    asm("cvt.rna.tf32.f32 %0, %1;" : "=r"(u) : "f"(f));
    return u;
}
__device__ __forceinline__ void mma_tf32(float* c, const uint32_t* a, const uint32_t* b) {
    asm volatile(
        "mma.sync.aligned.m16n8k8.row.col.f32.tf32.tf32.f32 "
        "{%0,%1,%2,%3}, {%4,%5,%6,%7}, {%8,%9}, {%0,%1,%2,%3};"
        : "+f"(c[0]), "+f"(c[1]), "+f"(c[2]), "+f"(c[3])
        : "r"(a[0]), "r"(a[1]), "r"(a[2]), "r"(a[3]), "r"(b[0]), "r"(b[1]));
}
__device__ __forceinline__ void mma_bf16(float* c, const uint32_t* a, const uint32_t* b) {
    asm volatile(
        "mma.sync.aligned.m16n8k16.row.col.f32.bf16.bf16.f32 "
        "{%0,%1,%2,%3}, {%4,%5,%6,%7}, {%8,%9}, {%0,%1,%2,%3};"
        : "+f"(c[0]), "+f"(c[1]), "+f"(c[2]), "+f"(c[3])
        : "r"(a[0]), "r"(a[1]), "r"(a[2]), "r"(a[3]), "r"(b[0]), "r"(b[1]));
}
__device__ __forceinline__ uint32_t bf16_split_pack(float x) {
    __nv_bfloat16 h = __float2bfloat16(x);
    float hf = __bfloat162float(h);
    __nv_bfloat16 l = __float2bfloat16(x - hf);
    return (uint32_t)__bfloat16_as_ushort(h) |
           ((uint32_t)__bfloat16_as_ushort(l) << 16);
}

// ---------------- small kernels ----------------
__global__ void k_xt(const float* __restrict__ x) {
    int i = blockIdx.x * 256 + threadIdx.x;
    if (i < TIN * BATCH * FIN) {
        int k = i & 63, r = i >> 6;
        int t = r >> 6, b = r & 63;
        g_xT[i] = x[(b * TIN + t) * FIN + k];
    }
}
__global__ void k_init() {
    int i = blockIdx.x * 256 + threadIdx.x;
    if (i < BATCH * HID) { g_hA[i] = 0.0f; g_hApk[i] = 0u; }
    if (blockIdx.x == 0 && threadIdx.x < 8) g_ctr[threadIdx.x] = 0u;
}
__global__ void k_zero() { if (threadIdx.x < 8) g_ctr[threadIdx.x] = 0u; }
__global__ void k_combine(const float* __restrict__ blin, float* __restrict__ out) {
    int i = blockIdx.x * 256 + threadIdx.x;
    if (i < BATCH * NLIN) {
        int b = i >> 12, m = i & 4095;
        float s = blin[m];
#pragma unroll
        for (int ks = 0; ks < KSPLIT; ++ks)
            s += g_part[((size_t)ks * BATCH + b) * NLIN + m];
        out[i] = s;
    }
}

// ---------------- fp32 SIMT GEMM (pre-projections, proven) ----------------
__device__ __forceinline__ void gemm64_core(
    const float* __restrict__ A, int lda,
    const float* __restrict__ W, int ldw,
    float* __restrict__ C, int ldc, int kcount,
    const float* __restrict__ bias1, const float* __restrict__ bias2)
{
    __shared__ __align__(16) float As[2][32 * 68];
    __shared__ __align__(16) float Ws[2][32 * 68];
    const int tid = threadIdx.x;
    const int n0 = blockIdx.x * 64;
    const int mbase = blockIdx.z * 64;
    const int b0 = (tid & 15) * 4, nt = (tid >> 4) * 4;
    float acc[4][4];
#pragma unroll
    for (int i = 0; i < 4; ++i)
#pragma unroll
        for (int j = 0; j < 4; ++j) acc[i][j] = 0.0f;
    const int ntiles = kcount >> 5;
#pragma unroll
    for (int e = 0; e < 8; ++e) {
        int idx = tid + e * 256, m = idx >> 5, k = idx & 31;
        As[0][k * 68 + m] = A[(size_t)(mbase + m) * lda + k];
        Ws[0][k * 68 + m] = W[(size_t)(n0 + m) * ldw + k];
    }
    __syncthreads();
    for (int kt = 0; kt < ntiles; ++kt) {
        float pfA[8], pfW[8];
        const bool more = (kt + 1 < ntiles);
        if (more) {
            int ko = (kt + 1) << 5;
#pragma unroll
            for (int e = 0; e < 8; ++e) {
                int idx = tid + e * 256, m = idx >> 5, k = idx & 31;
                pfA[e] = A[(size_t)(mbase + m) * lda + ko + k];
                pfW[e] = W[(size_t)(n0 + m) * ldw + ko + k];
            }
        }
        const float* as = As[kt & 1];
        const float* wz = Ws[kt & 1];
#pragma unroll
        for (int k = 0; k < 32; ++k) {
            float4 av = *(const float4*)(as + k * 68 + b0);
            float4 wv = *(const float4*)(wz + k * 68 + nt);
            float aa[4] = {av.x, av.y, av.z, av.w};
            float ww[4] = {wv.x, wv.y, wv.z, wv.w};
#pragma unroll
            for (int i = 0; i < 4; ++i)
#pragma unroll
                for (int j = 0; j < 4; ++j)
                    acc[i][j] = fmaf(aa[i], ww[j], acc[i][j]);
        }
        if (more) {
            float* dA = As[(kt + 1) & 1];
            float* dW = Ws[(kt + 1) & 1];
#pragma unroll
            for (int e = 0; e < 8; ++e) {
                int idx = tid + e * 256, m = idx >> 5, k = idx & 31;
                dA[k * 68 + m] = pfA[e];
                dW[k * 68 + m] = pfW[e];
            }
        }
        __syncthreads();
    }
#pragma unroll
    for (int i = 0; i < 4; ++i) {
        int m = mbase + b0 + i;
#pragma unroll
        for (int j = 0; j < 4; ++j) {
            int n = n0 + nt + j;
            C[(size_t)m * ldc + n] = acc[i][j] + bias1[n] + bias2[n];
        }
    }
}
__global__ void __launch_bounds__(256) k_pre1(const float* __restrict__ W,
                                              const float* __restrict__ b1,
                                              const float* __restrict__ b2) {
    gemm64_core(g_xT, FIN, W, FIN, g_pre1, G4, FIN, b1, b2);
}
__global__ void __launch_bounds__(256) k_pre2(const float* __restrict__ W,
                                              const float* __restrict__ b1,
                                              const float* __restrict__ b2) {
    gemm64_core(g_hA, HID, W, HID, g_pre2, G4, HID, b1, b2);
}

// ---------------- tf32 mma.sync linear (proven R7/R8) ----------------
__global__ void __launch_bounds__(256, 1) k_lin_mma(const float* __restrict__ Wl) {
    extern __shared__ __align__(16) uint32_t lsm[];
    const int tid = threadIdx.x, wid = tid >> 5, lane = tid & 31;
    const int gid = lane >> 2, tig = lane & 3;
    const int m0 = blockIdx.x * 128;
    const int ks = blockIdx.y;
    const int k0b = ks * KPER;

    float acc[4][2][4];
#pragma unroll
    for (int mt = 0; mt < 4; ++mt)
#pragma unroll
        for (int nt = 0; nt < 2; ++nt)
#pragma unroll
            for (int r = 0; r < 4; ++r) acc[mt][nt][r] = 0.0f;
    {
        uint32_t* A0 = lsm;
        uint32_t* W0 = lsm + 4352;
#pragma unroll
        for (int e = 0; e < 4; ++e) {
            int idx = tid + e * 256, row = idx >> 4, c4 = idx & 15;
            float4 v = *(const float4*)(g_seq + (size_t)row * KLIN + k0b + c4 * 4);
            uint32_t* d = A0 + row * 68 + c4 * 4;
            d[0] = f2tf(v.x); d[1] = f2tf(v.y); d[2] = f2tf(v.z); d[3] = f2tf(v.w);
        }
#pragma unroll
        for (int e = 0; e < 8; ++e) {
            int idx = tid + e * 256, row = idx >> 4, c4 = idx & 15;
            float4 v = *(const float4*)(Wl + (size_t)(m0 + row) * KLIN + k0b + c4 * 4);
            uint32_t* d = W0 + row * 68 + c4 * 4;
            d[0] = f2tf(v.x); d[1] = f2tf(v.y); d[2] = f2tf(v.z); d[3] = f2tf(v.w);
        }
    }
    __syncthreads();

    for (int ch = 0; ch < LNCH; ++ch) {
        const int buf = ch & 1;
        const bool more = (ch + 1 < LNCH);
        float4 fa[4], fw[8];
        if (more) {
            int k0 = k0b + (ch + 1) * LCHUNK;
#pragma unroll
            for (int e = 0; e < 4; ++e) {
                int idx = tid + e * 256, row = idx >> 4, c4 = idx & 15;
                fa[e] = *(const float4*)(g_seq + (size_t)row * KLIN + k0 + c4 * 4);
            }
#pragma unroll
            for (int e = 0; e < 8; ++e) {
                int idx = tid + e * 256, row = idx >> 4, c4 = idx & 15;
                fw[e] = *(const float4*)(Wl + (size_t)(m0 + row) * KLIN + k0 + c4 * 4);
            }
        }
        const uint32_t* As = lsm + buf * 13056;
        const uint32_t* Ws = lsm + buf * 13056 + 4352;
#pragma unroll
        for (int kk = 0; kk < 8; ++kk) {
            uint32_t a[4][4], b[2][2];
#pragma unroll
            for (int mt = 0; mt < 4; ++mt) {
                const uint32_t* ap = As + (mt * 16 + gid) * 68 + kk * 8 + tig;
                a[mt][0] = ap[0];
                a[mt][1] = ap[8 * 68];
                a[mt][2] = ap[4];
                a[mt][3] = ap[8 * 68 + 4];
            }
#pragma unroll
            for (int nt = 0; nt < 2; ++nt) {
                const uint32_t* bp = Ws + (wid * 16 + nt * 8 + gid) * 68 + kk * 8 + tig;
                b[nt][0] = bp[0];
                b[nt][1] = bp[4];
            }
#pragma unroll
            for (int mt = 0; mt < 4; ++mt)
#pragma unroll
                for (int nt = 0; nt < 2; ++nt)
                    mma_tf32(acc[mt][nt], a[mt], b[nt]);
        }
        if (more) {
            uint32_t* A1 = lsm + (buf ^ 1) * 13056;
            uint32_t* W1 = A1 + 4352;
#pragma unroll
            for (int e = 0; e < 4; ++e) {
                int idx = tid + e * 256, row = idx >> 4, c4 = idx & 15;
                uint32_t* d = A1 + row * 68 + c4 * 4;
                d[0] = f2tf(fa[e].x); d[1] = f2tf(fa[e].y);
                d[2] = f2tf(fa[e].z); d[3] = f2tf(fa[e].w);
            }
#pragma unroll
            for (int e = 0; e < 8; ++e) {
                int idx = tid + e * 256, row = idx >> 4, c4 = idx & 15;
                uint32_t* d = W1 + row * 68 + c4 * 4;
                d[0] = f2tf(fw[e].x); d[1] = f2tf(fw[e].y);
                d[2] = f2tf(fw[e].z); d[3] = f2tf(fw[e].w);
            }
        }
        __syncthreads();
    }
#pragma unroll
    for (int mt = 0; mt < 4; ++mt) {
#pragma unroll
        for (int nt = 0; nt < 2; ++nt) {
            int brow = mt * 16 + gid;
            int m = m0 + wid * 16 + nt * 8 + 2 * tig;
            float* base0 = &g_part[((size_t)ks * BATCH + brow) * NLIN + m];
            float* base1 = &g_part[((size_t)ks * BATCH + brow + 8) * NLIN + m];
            *(float2*)base0 = make_float2(acc[mt][nt][0], acc[mt][nt][1]);
            *(float2*)base1 = make_float2(acc[mt][nt][2], acc[mt][nt][3]);
        }
    }
}

// ---------------- bf16 2-term tensor-core LSTM recurrence ----------------
// 128 blocks x 256 thr. Block owns 4 h-cols (16 gate rows). W frags (bf16x2
// hi/lo planes, 32 KB) + full-K A planes (130 KB) in smem. h circulates as
// packed u32 (bf16 hi|lo). Warp = (mg 0..3, kh 0..1).
__device__ __forceinline__ void lstm_mma(
    const float* __restrict__ Whh,
    const float* __restrict__ pre, int preStride,
    uint32_t* __restrict__ hApk, float* __restrict__ hAf,
    uint32_t* __restrict__ hBpk, float* __restrict__ hBf,
    float* __restrict__ cbuf, int loadC, int saveC,
    float* __restrict__ seqOut, int nsteps)
{
    extern __shared__ __align__(16) uint32_t sm[];
    uint32_t* wsf = sm + WS_OFF;
    uint32_t* Ahi = sm + AHI_OFF;
    uint32_t* Alo = sm + ALO_OFF;
    float* Csm = (float*)(sm + CSM_OFF);
    float* red = (float*)(sm + RED_OFF);

    const int tid = threadIdx.x;
    const int bk = blockIdx.x;
    const int hc0 = bk * 4;
    const int lane = tid & 31, wid = tid >> 5;
    const int mg = wid >> 1, kh = wid & 1;
    const int gid = lane >> 2, tig = lane & 3;
    const int b = tid & 63, chn = (tid >> 6) & 3;
    const int hcol = hc0 + chn;
    const int srow = tid & 63, sseg = tid >> 6;

    // one-time W frag build: fragId = (ktile*2+nt)*2+plane
    for (int idx = tid; idx < 8192; idx += 256) {
        int fragId = idx >> 6, rem = idx & 63;
        int ln = rem >> 1, rg = rem & 1;
        int plane = fragId & 1, nt = (fragId >> 1) & 1, ktile = fragId >> 2;
        int n = nt * 8 + (ln >> 2);
        int q = n >> 2, cc = n & 3;
        int k = ktile * 16 + (ln & 3) * 2 + rg * 8;
        const float* wr = Whh + (size_t)(q * HID + hc0 + cc) * HID + k;
        uint32_t p0 = bf16_split_pack(wr[0]);
        uint32_t p1 = bf16_split_pack(wr[1]);
        wsf[idx] = (plane == 0) ? __byte_perm(p0, p1, 0x5410)
                                : __byte_perm(p0, p1, 0x7632);
    }
    __syncthreads();

    float creg = loadC ? cbuf[b * HID + hcol] : 0.0f;

    for (int t = 0; t < nsteps; ++t) {
        const uint32_t* hin = (t & 1) ? hBpk : hApk;
        uint32_t* houtP = (t & 1) ? hApk : hBpk;
        float* houtF = (t & 1) ? hAf : hBf;

        float p0, p1, p2, p3;
        {
            const float* pp = pre + (size_t)t * preStride + b * G4 + hcol;
            p0 = __ldg(pp); p1 = __ldg(pp + 512);
            p2 = __ldg(pp + 1024); p3 = __ldg(pp + 1536);
        }

        // stage full K: split packed h into hi/lo bf16x2 planes
        {
            const uint4* src = (const uint4*)(hin + srow * 512 + sseg * 128);
            uint32_t* dh = Ahi + srow * 260 + sseg * 64;
            uint32_t* dl = Alo + srow * 260 + sseg * 64;
#pragma unroll 8
            for (int i = 0; i < 32; ++i) {
                uint4 v = __ldcg(src + i);
                uint32_t h0 = __byte_perm(v.x, v.y, 0x5410);
                uint32_t h1 = __byte_perm(v.z, v.w, 0x5410);
                uint32_t l0 = __byte_perm(v.x, v.y, 0x7632);
                uint32_t l1 = __byte_perm(v.z, v.w, 0x7632);
                *(uint2*)(dh + i * 2) = make_uint2(h0, h1);
                *(uint2*)(dl + i * 2) = make_uint2(l0, l1);
            }
        }
        __syncthreads();

        float acc[2][4];
#pragma unroll
        for (int nt = 0; nt < 2; ++nt)
#pragma unroll
            for (int r = 0; r < 4; ++r) acc[nt][r] = 0.f;

#pragma unroll
        for (int kt = 0; kt < 16; ++kt) {
            int ktg = kh * 16 + kt;
            int abase = (mg * 16 + gid) * 260 + ktg * 8 + tig;
            uint32_t ah[4], al[4];
            ah[0] = Ahi[abase];       ah[1] = Ahi[abase + 8 * 260];
            ah[2] = Ahi[abase + 4];   ah[3] = Ahi[abase + 8 * 260 + 4];
            al[0] = Alo[abase];       al[1] = Alo[abase + 8 * 260];
            al[2] = Alo[abase + 4];   al[3] = Alo[abase + 8 * 260 + 4];
#pragma unroll
            for (int nt = 0; nt < 2; ++nt) {
                int fb = ((ktg * 2 + nt) * 2) * 64 + lane * 2;
                uint32_t bh[2], bl[2];
                *(uint2*)bh = *(const uint2*)(wsf + fb);
                *(uint2*)bl = *(const uint2*)(wsf + fb + 64);
                mma_bf16(acc[nt], ah, bh);
                mma_bf16(acc[nt], ah, bl);
                mma_bf16(acc[nt], al, bh);
            }
        }

        if (kh == 1) {
#pragma unroll
            for (int nt = 0; nt < 2; ++nt)
                *(float4*)(red + (mg * 32 + lane) * 8 + nt * 4) =
                    make_float4(acc[nt][0], acc[nt][1], acc[nt][2], acc[nt][3]);
        }
        __syncthreads();
        if (kh == 0) {
#pragma unroll
            for (int nt = 0; nt < 2; ++nt) {
                float4 r4 = *(const float4*)(red + (mg * 32 + lane) * 8 + nt * 4);
                int row = mg * 16 + gid, col = nt * 8 + 2 * tig;
                Csm[row * 17 + col]           = acc[nt][0] + r4.x;
                Csm[row * 17 + col + 1]       = acc[nt][1] + r4.y;
                Csm[(row + 8) * 17 + col]     = acc[nt][2] + r4.z;
                Csm[(row + 8) * 17 + col + 1] = acc[nt][3] + r4.w;
            }
        }
        __syncthreads();

        {
            float a0 = Csm[b * 17 + 0 + chn] + p0;
            float a1 = Csm[b * 17 + 4 + chn] + p1;
            float a2 = Csm[b * 17 + 8 + chn] + p2;
            float a3 = Csm[b * 17 + 12 + chn] + p3;
            float si = 1.f / (1.f + __expf(-a0));
            float sf = 1.f / (1.f + __expf(-a1));
            float so = 1.f / (1.f + __expf(-a3));
            creg = sf * creg + si * tanhf(a2);
            float hnew = so * tanhf(creg);
            houtP[b * HID + hcol] = bf16_split_pack(hnew);
            houtF[b * HID + hcol] = hnew;
            if (seqOut) seqOut[(size_t)b * KLIN + t * HID + hcol] = hnew;
        }
        __syncthreads();

        if (t + 1 < nsteps) {
            if (tid == 0) {
                __threadfence();
                atomicAdd(&g_ctr[bk & 7], 1u);
                unsigned need = 16u * (unsigned)(t + 1);
                for (;;) {
                    uint4 c0 = __ldcv((const uint4*)g_ctr);
                    uint4 c1 = __ldcv((const uint4*)g_ctr + 1);
                    if (c0.x >= need && c0.y >= need && c0.z >= need &&
                        c0.w >= need && c1.x >= need && c1.y >= need &&
                        c1.z >= need && c1.w >= need) break;
                    __nanosleep(64);
                }
                __threadfence();
            }
            __syncthreads();
        }
    }
    if (saveC) cbuf[b * HID + hcol] = creg;
}

__global__ void __launch_bounds__(256, 1) k_enc(const float* __restrict__ Whh) {
    lstm_mma(Whh, g_pre1, BATCH * G4, g_hApk, g_hA, g_hBpk, g_hB,
             g_c, 0, 1, nullptr, TIN);
}
__global__ void __launch_bounds__(256, 1) k_dec(const float* __restrict__ Whh) {
    lstm_mma(Whh, g_pre2, 0, g_hApk, g_hA, g_hBpk, g_hB,
             g_c, 1, 0, g_seq, TOUTN);
}

extern "C" void kernel_launch(void* const* d_in, const int* in_sizes, int n_in,
                              void* d_out, int out_size) {
    const float* x    = (const float*)d_in[0];
    const float* Wih1 = (const float*)d_in[1];
    const float* Whh1 = (const float*)d_in[2];
    const float* bih1 = (const float*)d_in[3];
    const float* bhh1 = (const float*)d_in[4];
    const float* Wih2 = (const float*)d_in[5];
    const float* Whh2 = (const float*)d_in[6];
    const float* bih2 = (const float*)d_in[7];
    const float* bhh2 = (const float*)d_in[8];
    const float* Wlin = (const float*)d_in[9];
    const float* blin = (const float*)d_in[10];
    float* out = (float*)d_out;

    const int lstmSmem = DSMW * 4;        // 168192
    const int linSmem  = 2 * 13056 * 4;   // 104448
    cudaFuncSetAttribute(k_enc, cudaFuncAttributeMaxDynamicSharedMemorySize, lstmSmem);
    cudaFuncSetAttribute(k_dec, cudaFuncAttributeMaxDynamicSharedMemorySize, lstmSmem);
    cudaFuncSetAttribute(k_lin_mma, cudaFuncAttributeMaxDynamicSharedMemorySize, linSmem);

    k_xt<<<(TIN * BATCH * FIN + 255) / 256, 256>>>(x);
    k_init<<<(BATCH * HID + 255) / 256, 256>>>();

    dim3 gpre1(G4 / 64, 1, (TIN * BATCH) / 64);
    k_pre1<<<gpre1, 256>>>(Wih1, bih1, bhh1);

    k_enc<<<NBLK, 256, lstmSmem>>>(Whh1);   // TIN even: final h in A-set

    dim3 gpre2(G4 / 64, 1, 1);
    k_pre2<<<gpre2, 256>>>(Wih2, bih2, bhh2);

    k_zero<<<1, 32>>>();
    k_dec<<<NBLK, 256, lstmSmem>>>(Whh2);

    dim3 glin(NLIN / 128, KSPLIT);
    k_lin_mma<<<glin, 256, linSmem>>>(Wlin);

    k_combine<<<(BATCH * NLIN + 255) / 256, 256>>>(blin, out);
}

// round 13
// speedup vs baseline: 2.2555x; 2.2555x over previous
#include <cuda_runtime.h>
#include <cuda_bf16.h>
#include <cstdint>

#define BATCH 64
#define TIN   128
#define FIN   64
#define HID   512
#define G4    2048
#define TOUTN 64
#define KLIN  32768
#define NLIN  4096

#define KSPLIT 4
#define KPER   (KLIN / KSPLIT)
#define LCHUNK 64
#define LNCH   (KPER / LCHUNK)

// k_step smem (u32 words)
#define WS_OFF  0
#define AHI_OFF 8192
#define ALO_OFF (AHI_OFF + 16640)
#define CSM_OFF (ALO_OFF + 16640)
#define RED_OFF (CSM_OFF + 1152)
#define DSMW    (RED_OFF + 1024)    // 43648 u32 = 174592 B

__device__ float g_xT[TIN * BATCH * FIN];
__device__ float g_pre1[TIN * BATCH * G4];
__device__ float g_pre2[BATCH * G4];
__device__ float g_hA[BATCH * HID];
__device__ float g_hB[BATCH * HID];
__device__ unsigned short g_hAhi16[BATCH * HID];
__device__ unsigned short g_hAlo16[BATCH * HID];
__device__ unsigned short g_hBhi16[BATCH * HID];
__device__ unsigned short g_hBlo16[BATCH * HID];
__device__ float g_c[BATCH * HID];
__device__ float g_seq[BATCH * KLIN];
__device__ float g_part[KSPLIT * BATCH * NLIN];
__device__ uint32_t g_wf[2][128 * 8192];   // frag-major bf16 hi/lo W planes

__device__ __forceinline__ uint32_t f2tf(float f) {
    uint32_t u;
    asm("cvt.rna.tf32.f32 %0, %1;" : "=r"(u) : "f"(f));
    return u;
}
__device__ __forceinline__ void mma_tf32(float* c, const uint32_t* a, const uint32_t* b) {
    asm volatile(
        "mma.sync.aligned.m16n8k8.row.col.f32.tf32.tf32.f32 "
        "{%0,%1,%2,%3}, {%4,%5,%6,%7}, {%8,%9}, {%0,%1,%2,%3};"
        : "+f"(c[0]), "+f"(c[1]), "+f"(c[2]), "+f"(c[3])
        : "r"(a[0]), "r"(a[1]), "r"(a[2]), "r"(a[3]), "r"(b[0]), "r"(b[1]));
}
__device__ __forceinline__ void mma_bf16(float* c, const uint32_t* a, const uint32_t* b) {
    asm volatile(
        "mma.sync.aligned.m16n8k16.row.col.f32.bf16.bf16.f32 "
        "{%0,%1,%2,%3}, {%4,%5,%6,%7}, {%8,%9}, {%0,%1,%2,%3};"
        : "+f"(c[0]), "+f"(c[1]), "+f"(c[2]), "+f"(c[3])
        : "r"(a[0]), "r"(a[1]), "r"(a[2]), "r"(a[3]), "r"(b[0]), "r"(b[1]));
}
__device__ __forceinline__ uint32_t bf16_split_pack(float x) {
    __nv_bfloat16 h = __float2bfloat16(x);
    float hf = __bfloat162float(h);
    __nv_bfloat16 l = __float2bfloat16(x - hf);
    return (uint32_t)__bfloat16_as_ushort(h) |
           ((uint32_t)__bfloat16_as_ushort(l) << 16);
}

// ---------------- small kernels ----------------
__global__ void k_xt(const float* __restrict__ x) {
    int i = blockIdx.x * 256 + threadIdx.x;
    if (i < TIN * BATCH * FIN) {
        int k = i & 63, r = i >> 6;
        int t = r >> 6, b = r & 63;
        g_xT[i] = x[(b * TIN + t) * FIN + k];
    }
}
__global__ void k_init() {
    int i = blockIdx.x * 256 + threadIdx.x;
    if (i < BATCH * HID) {
        g_hAhi16[i] = 0; g_hAlo16[i] = 0; g_c[i] = 0.0f;
    }
}
__global__ void k_combine(const float* __restrict__ blin, float* __restrict__ out) {
    int i = blockIdx.x * 256 + threadIdx.x;
    if (i < BATCH * NLIN) {
        int b = i >> 12, m = i & 4095;
        float s = blin[m];
#pragma unroll
        for (int ks = 0; ks < KSPLIT; ++ks)
            s += g_part[((size_t)ks * BATCH + b) * NLIN + m];
        out[i] = s;
    }
}

// ---------------- W frag prep (R10-verified layout) ----------------
__global__ void __launch_bounds__(256) k_prepW(const float* __restrict__ W1,
                                               const float* __restrict__ W2) {
    int layer = blockIdx.x >> 7;
    int bk = blockIdx.x & 127;
    const float* Whh = layer ? W2 : W1;
    uint32_t* dst = g_wf[layer] + (size_t)bk * 8192;
    int hc0 = bk * 4;
    for (int idx = threadIdx.x; idx < 8192; idx += 256) {
        int fragId = idx >> 6, rem = idx & 63;
        int ln = rem >> 1, rg = rem & 1;
        int plane = fragId & 1, nt = (fragId >> 1) & 1, ktile = fragId >> 2;
        int n = nt * 8 + (ln >> 2);
        int q = n >> 2, cc = n & 3;
        int k = ktile * 16 + (ln & 3) * 2 + rg * 8;
        const float* wr = Whh + (size_t)(q * HID + hc0 + cc) * HID + k;
        uint32_t p0 = bf16_split_pack(wr[0]);
        uint32_t p1 = bf16_split_pack(wr[1]);
        dst[idx] = (plane == 0) ? __byte_perm(p0, p1, 0x5410)
                                : __byte_perm(p0, p1, 0x7632);
    }
}

// ---------------- fp32 SIMT GEMM (pre-projections, proven) ----------------
__device__ __forceinline__ void gemm64_core(
    const float* __restrict__ A, int lda,
    const float* __restrict__ W, int ldw,
    float* __restrict__ C, int ldc, int kcount,
    const float* __restrict__ bias1, const float* __restrict__ bias2)
{
    __shared__ __align__(16) float As[2][32 * 68];
    __shared__ __align__(16) float Ws[2][32 * 68];
    const int tid = threadIdx.x;
    const int n0 = blockIdx.x * 64;
    const int mbase = blockIdx.z * 64;
    const int b0 = (tid & 15) * 4, nt = (tid >> 4) * 4;
    float acc[4][4];
#pragma unroll
    for (int i = 0; i < 4; ++i)
#pragma unroll
        for (int j = 0; j < 4; ++j) acc[i][j] = 0.0f;
    const int ntiles = kcount >> 5;
#pragma unroll
    for (int e = 0; e < 8; ++e) {
        int idx = tid + e * 256, m = idx >> 5, k = idx & 31;
        As[0][k * 68 + m] = A[(size_t)(mbase + m) * lda + k];
        Ws[0][k * 68 + m] = W[(size_t)(n0 + m) * ldw + k];
    }
    __syncthreads();
    for (int kt = 0; kt < ntiles; ++kt) {
        float pfA[8], pfW[8];
        const bool more = (kt + 1 < ntiles);
        if (more) {
            int ko = (kt + 1) << 5;
#pragma unroll
            for (int e = 0; e < 8; ++e) {
                int idx = tid + e * 256, m = idx >> 5, k = idx & 31;
                pfA[e] = A[(size_t)(mbase + m) * lda + ko + k];
                pfW[e] = W[(size_t)(n0 + m) * ldw + ko + k];
            }
        }
        const float* as = As[kt & 1];
        const float* wz = Ws[kt & 1];
#pragma unroll
        for (int k = 0; k < 32; ++k) {
            float4 av = *(const float4*)(as + k * 68 + b0);
            float4 wv = *(const float4*)(wz + k * 68 + nt);
            float aa[4] = {av.x, av.y, av.z, av.w};
            float ww[4] = {wv.x, wv.y, wv.z, wv.w};
#pragma unroll
            for (int i = 0; i < 4; ++i)
#pragma unroll
                for (int j = 0; j < 4; ++j)
                    acc[i][j] = fmaf(aa[i], ww[j], acc[i][j]);
        }
        if (more) {
            float* dA = As[(kt + 1) & 1];
            float* dW = Ws[(kt + 1) & 1];
#pragma unroll
            for (int e = 0; e < 8; ++e) {
                int idx = tid + e * 256, m = idx >> 5, k = idx & 31;
                dA[k * 68 + m] = pfA[e];
                dW[k * 68 + m] = pfW[e];
            }
        }
        __syncthreads();
    }
#pragma unroll
    for (int i = 0; i < 4; ++i) {
        int m = mbase + b0 + i;
#pragma unroll
        for (int j = 0; j < 4; ++j) {
            int n = n0 + nt + j;
            C[(size_t)m * ldc + n] = acc[i][j] + bias1[n] + bias2[n];
        }
    }
}
__global__ void __launch_bounds__(256) k_pre1(const float* __restrict__ W,
                                              const float* __restrict__ b1,
                                              const float* __restrict__ b2) {
    gemm64_core(g_xT, FIN, W, FIN, g_pre1, G4, FIN, b1, b2);
}
__global__ void __launch_bounds__(256) k_pre2(const float* __restrict__ W,
                                              const float* __restrict__ b1,
                                              const float* __restrict__ b2) {
    gemm64_core(g_hA, HID, W, HID, g_pre2, G4, HID, b1, b2);
}

// ---------------- tf32 mma.sync linear (proven R7/R8) ----------------
__global__ void __launch_bounds__(256, 1) k_lin_mma(const float* __restrict__ Wl) {
    extern __shared__ __align__(16) uint32_t lsm[];
    const int tid = threadIdx.x, wid = tid >> 5, lane = tid & 31;
    const int gid = lane >> 2, tig = lane & 3;
    const int m0 = blockIdx.x * 128;
    const int ks = blockIdx.y;
    const int k0b = ks * KPER;

    float acc[4][2][4];
#pragma unroll
    for (int mt = 0; mt < 4; ++mt)
#pragma unroll
        for (int nt = 0; nt < 2; ++nt)
#pragma unroll
            for (int r = 0; r < 4; ++r) acc[mt][nt][r] = 0.0f;
    {
        uint32_t* A0 = lsm;
        uint32_t* W0 = lsm + 4352;
#pragma unroll
        for (int e = 0; e < 4; ++e) {
            int idx = tid + e * 256, row = idx >> 4, c4 = idx & 15;
            float4 v = *(const float4*)(g_seq + (size_t)row * KLIN + k0b + c4 * 4);
            uint32_t* d = A0 + row * 68 + c4 * 4;
            d[0] = f2tf(v.x); d[1] = f2tf(v.y); d[2] = f2tf(v.z); d[3] = f2tf(v.w);
        }
#pragma unroll
        for (int e = 0; e < 8; ++e) {
            int idx = tid + e * 256, row = idx >> 4, c4 = idx & 15;
            float4 v = *(const float4*)(Wl + (size_t)(m0 + row) * KLIN + k0b + c4 * 4);
            uint32_t* d = W0 + row * 68 + c4 * 4;
            d[0] = f2tf(v.x); d[1] = f2tf(v.y); d[2] = f2tf(v.z); d[3] = f2tf(v.w);
        }
    }
    __syncthreads();

    for (int ch = 0; ch < LNCH; ++ch) {
        const int buf = ch & 1;
        const bool more = (ch + 1 < LNCH);
        float4 fa[4], fw[8];
        if (more) {
            int k0 = k0b + (ch + 1) * LCHUNK;
#pragma unroll
            for (int e = 0; e < 4; ++e) {
                int idx = tid + e * 256, row = idx >> 4, c4 = idx & 15;
                fa[e] = *(const float4*)(g_seq + (size_t)row * KLIN + k0 + c4 * 4);
            }
#pragma unroll
            for (int e = 0; e < 8; ++e) {
                int idx = tid + e * 256, row = idx >> 4, c4 = idx & 15;
                fw[e] = *(const float4*)(Wl + (size_t)(m0 + row) * KLIN + k0 + c4 * 4);
            }
        }
        const uint32_t* As = lsm + buf * 13056;
        const uint32_t* Ws = lsm + buf * 13056 + 4352;
#pragma unroll
        for (int kk = 0; kk < 8; ++kk) {
            uint32_t a[4][4], b[2][2];
#pragma unroll
            for (int mt = 0; mt < 4; ++mt) {
                const uint32_t* ap = As + (mt * 16 + gid) * 68 + kk * 8 + tig;
                a[mt][0] = ap[0];
                a[mt][1] = ap[8 * 68];
                a[mt][2] = ap[4];
                a[mt][3] = ap[8 * 68 + 4];
            }
#pragma unroll
            for (int nt = 0; nt < 2; ++nt) {
                const uint32_t* bp = Ws + (wid * 16 + nt * 8 + gid) * 68 + kk * 8 + tig;
                b[nt][0] = bp[0];
                b[nt][1] = bp[4];
            }
#pragma unroll
            for (int mt = 0; mt < 4; ++mt)
#pragma unroll
                for (int nt = 0; nt < 2; ++nt)
                    mma_tf32(acc[mt][nt], a[mt], b[nt]);
        }
        if (more) {
            uint32_t* A1 = lsm + (buf ^ 1) * 13056;
            uint32_t* W1 = A1 + 4352;
#pragma unroll
            for (int e = 0; e < 4; ++e) {
                int idx = tid + e * 256, row = idx >> 4, c4 = idx & 15;
                uint32_t* d = A1 + row * 68 + c4 * 4;
                d[0] = f2tf(fa[e].x); d[1] = f2tf(fa[e].y);
                d[2] = f2tf(fa[e].z); d[3] = f2tf(fa[e].w);
            }
#pragma unroll
            for (int e = 0; e < 8; ++e) {
                int idx = tid + e * 256, row = idx >> 4, c4 = idx & 15;
                uint32_t* d = W1 + row * 68 + c4 * 4;
                d[0] = f2tf(fw[e].x); d[1] = f2tf(fw[e].y);
                d[2] = f2tf(fw[e].z); d[3] = f2tf(fw[e].w);
            }
        }
        __syncthreads();
    }
#pragma unroll
    for (int mt = 0; mt < 4; ++mt) {
#pragma unroll
        for (int nt = 0; nt < 2; ++nt) {
            int brow = mt * 16 + gid;
            int m = m0 + wid * 16 + nt * 8 + 2 * tig;
            float* base0 = &g_part[((size_t)ks * BATCH + brow) * NLIN + m];
            float* base1 = &g_part[((size_t)ks * BATCH + brow + 8) * NLIN + m];
            *(float2*)base0 = make_float2(acc[mt][nt][0], acc[mt][nt][1]);
            *(float2*)base1 = make_float2(acc[mt][nt][2], acc[mt][nt][3]);
        }
    }
}

// ---------------- one LSTM time-step per launch (R10-verified math) ----------------
__global__ void __launch_bounds__(256, 1) k_step(int layer, int t, int loadC,
                                                 int writeSeq) {
    extern __shared__ __align__(16) uint32_t sm[];
    uint32_t* wsf = sm + WS_OFF;
    uint32_t* Ahi = sm + AHI_OFF;
    uint32_t* Alo = sm + ALO_OFF;
    float* Csm = (float*)(sm + CSM_OFF);
    float* red = (float*)(sm + RED_OFF);

    const int tid = threadIdx.x;
    const int bk = blockIdx.x;
    const int hc0 = bk * 4;
    const int lane = tid & 31, wid = tid >> 5;
    const int mg = wid >> 1, kh = wid & 1;
    const int gid = lane >> 2, tig = lane & 3;
    const int b = tid & 63, chn = (tid >> 6) & 3;
    const int hcol = hc0 + chn;

    const unsigned short* hinHi = (t & 1) ? g_hBhi16 : g_hAhi16;
    const unsigned short* hinLo = (t & 1) ? g_hBlo16 : g_hAlo16;
    unsigned short* houtHi = (t & 1) ? g_hAhi16 : g_hBhi16;
    unsigned short* houtLo = (t & 1) ? g_hAlo16 : g_hBlo16;
    float* houtF = (t & 1) ? g_hA : g_hB;
    const float* pre = layer ? (g_pre2 + b * G4 + hcol)
                             : (g_pre1 + (size_t)t * (BATCH * G4) + b * G4 + hcol);

    // stage W frags (32 KB) + h planes (2x64 KB) into smem
    // each h plane: 64 rows x 256 u32 = 4096 uint4 -> 16 iterations of 256 thr
    {
        const uint4* wsrc = (const uint4*)(g_wf[layer] + (size_t)bk * 8192);
        uint4* wdst = (uint4*)wsf;
#pragma unroll
        for (int e = 0; e < 8; ++e)
            wdst[tid + e * 256] = __ldcg(wsrc + tid + e * 256);
#pragma unroll
        for (int e = 0; e < 16; ++e) {
            int idx = tid + e * 256;          // uint4 = 8 ushorts = 4 u32
            int row = idx >> 6, c8 = idx & 63;
            uint4 vh = __ldcg((const uint4*)(hinHi + row * 512) + c8);
            uint4 vl = __ldcg((const uint4*)(hinLo + row * 512) + c8);
            *(uint4*)(Ahi + row * 260 + c8 * 4) = vh;
            *(uint4*)(Alo + row * 260 + c8 * 4) = vl;
        }
    }
    float p0 = __ldg(pre), p1 = __ldg(pre + 512);
    float p2 = __ldg(pre + 1024), p3 = __ldg(pre + 1536);
    float creg = loadC ? g_c[b * HID + hcol] : 0.0f;
    __syncthreads();

    float acc[2][4];
#pragma unroll
    for (int nt = 0; nt < 2; ++nt)
#pragma unroll
        for (int r = 0; r < 4; ++r) acc[nt][r] = 0.f;

#pragma unroll
    for (int kt = 0; kt < 16; ++kt) {
        int ktg = kh * 16 + kt;
        int abase = (mg * 16 + gid) * 260 + ktg * 8 + tig;
        uint32_t ah[4], al[4];
        ah[0] = Ahi[abase];       ah[1] = Ahi[abase + 8 * 260];
        ah[2] = Ahi[abase + 4];   ah[3] = Ahi[abase + 8 * 260 + 4];
        al[0] = Alo[abase];       al[1] = Alo[abase + 8 * 260];
        al[2] = Alo[abase + 4];   al[3] = Alo[abase + 8 * 260 + 4];
#pragma unroll
        for (int nt = 0; nt < 2; ++nt) {
            int fb = ((ktg * 2 + nt) * 2) * 64 + lane * 2;
            uint32_t bh[2], bl[2];
            *(uint2*)bh = *(const uint2*)(wsf + fb);
            *(uint2*)bl = *(const uint2*)(wsf + fb + 64);
            mma_bf16(acc[nt], ah, bh);
            mma_bf16(acc[nt], ah, bl);
            mma_bf16(acc[nt], al, bh);
        }
    }

    if (kh == 1) {
#pragma unroll
        for (int nt = 0; nt < 2; ++nt)
            *(float4*)(red + (mg * 32 + lane) * 8 + nt * 4) =
                make_float4(acc[nt][0], acc[nt][1], acc[nt][2], acc[nt][3]);
    }
    __syncthreads();
    if (kh == 0) {
#pragma unroll
        for (int nt = 0; nt < 2; ++nt) {
            float4 r4 = *(const float4*)(red + (mg * 32 + lane) * 8 + nt * 4);
            int row = mg * 16 + gid, col = nt * 8 + 2 * tig;
            Csm[row * 17 + col]           = acc[nt][0] + r4.x;
            Csm[row * 17 + col + 1]       = acc[nt][1] + r4.y;
            Csm[(row + 8) * 17 + col]     = acc[nt][2] + r4.z;
            Csm[(row + 8) * 17 + col + 1] = acc[nt][3] + r4.w;
        }
    }
    __syncthreads();

    {
        float a0 = Csm[b * 17 + 0 + chn] + p0;
        float a1 = Csm[b * 17 + 4 + chn] + p1;
        float a2 = Csm[b * 17 + 8 + chn] + p2;
        float a3 = Csm[b * 17 + 12 + chn] + p3;
        float si = 1.f / (1.f + __expf(-a0));
        float sf = 1.f / (1.f + __expf(-a1));
        float so = 1.f / (1.f + __expf(-a3));
        creg = sf * creg + si * tanhf(a2);
        float hnew = so * tanhf(creg);
        g_c[b * HID + hcol] = creg;
        __nv_bfloat16 hh = __float2bfloat16(hnew);
        __nv_bfloat16 hl = __float2bfloat16(hnew - __bfloat162float(hh));
        houtHi[b * HID + hcol] = __bfloat16_as_ushort(hh);
        houtLo[b * HID + hcol] = __bfloat16_as_ushort(hl);
        houtF[b * HID + hcol] = hnew;
        if (writeSeq) g_seq[(size_t)b * KLIN + t * HID + hcol] = hnew;
    }
}

extern "C" void kernel_launch(void* const* d_in, const int* in_sizes, int n_in,
                              void* d_out, int out_size) {
    const float* x    = (const float*)d_in[0];
    const float* Wih1 = (const float*)d_in[1];
    const float* Whh1 = (const float*)d_in[2];
    const float* bih1 = (const float*)d_in[3];
    const float* bhh1 = (const float*)d_in[4];
    const float* Wih2 = (const float*)d_in[5];
    const float* Whh2 = (const float*)d_in[6];
    const float* bih2 = (const float*)d_in[7];
    const float* bhh2 = (const float*)d_in[8];
    const float* Wlin = (const float*)d_in[9];
    const float* blin = (const float*)d_in[10];
    float* out = (float*)d_out;

    const int stepSmem = DSMW * 4;        // 174592
    const int linSmem  = 2 * 13056 * 4;   // 104448
    cudaFuncSetAttribute(k_step, cudaFuncAttributeMaxDynamicSharedMemorySize, stepSmem);
    cudaFuncSetAttribute(k_lin_mma, cudaFuncAttributeMaxDynamicSharedMemorySize, linSmem);

    k_xt<<<(TIN * BATCH * FIN + 255) / 256, 256>>>(x);
    k_init<<<(BATCH * HID + 255) / 256, 256>>>();
    k_prepW<<<256, 256>>>(Whh1, Whh2);

    dim3 gpre1(G4 / 64, 1, (TIN * BATCH) / 64);
    k_pre1<<<gpre1, 256>>>(Wih1, bih1, bhh1);

    for (int t = 0; t < TIN; ++t)
        k_step<<<128, 256, stepSmem>>>(0, t, t > 0 ? 1 : 0, 0);
    // TIN=128 even -> final h in A-set (f32 in g_hA), c in g_c

    dim3 gpre2(G4 / 64, 1, 1);
    k_pre2<<<gpre2, 256>>>(Wih2, bih2, bhh2);

    for (int t = 0; t < TOUTN; ++t)
        k_step<<<128, 256, stepSmem>>>(1, t, 1, 1);

    dim3 glin(NLIN / 128, KSPLIT);
    k_lin_mma<<<glin, 256, linSmem>>>(Wlin);

    k_combine<<<(BATCH * NLIN + 255) / 256, 256>>>(blin, out);
}